// round 3
// baseline (speedup 1.0000x reference)
#include <cuda_runtime.h>
#include <cuda_bf16.h>

#define BATCH 16
#define MP 30      // max people
#define NJ 17      // joints
#define AD 17      // ae tag dim
#define RES 512
#define RR (RES*RES)

__global__ __launch_bounds__(512, 1)
void ae_loss_kernel(const float* __restrict__ tags,
                    const int*   __restrict__ joints,
                    float*       __restrict__ out)
{
    const int b   = blockIdx.x;
    const int tid = threadIdx.x;

    __shared__ float t_s[MP][NJ][AD];   // masked gathered tag vectors (valid*t)
    __shared__ float sqv[MP][NJ];       // valid * sum_{d1,d2}(t_d1-t_d2)^2
    __shared__ float validf[MP][NJ];
    __shared__ float safe_cnt[MP];
    __shared__ float pullp[MP];         // pull_p * person_valid
    __shared__ float pv[MP];            // person_valid
    __shared__ float mean_s[MP][AD];
    __shared__ float ntags_s;
    __shared__ float pull_s;
    __shared__ float push_acc;

    const float* tag_b = tags + (size_t)b * AD * RR;
    const int*   jt_b  = joints + b * MP * NJ * 2;

    if (tid == 0) push_acc = 0.0f;

    // ---- Phase 1: per-joint gather + per-joint pairwise-sq reduction ----
    if (tid < MP * NJ) {
        const int m = tid / NJ;
        const int j = tid % NJ;
        int idx = jt_b[tid * 2 + 0];
        int vis = jt_b[tid * 2 + 1];
        float valid = (vis > 0) ? 1.0f : 0.0f;

        int off = idx % RR;
        if (off < 0) off += RR;
        int x = off % RES;              // first spatial axis (torch convention)
        int y = off / RES;
        const float* p = tag_b + (size_t)x * RES + y;

        float s1 = 0.0f, s2 = 0.0f;
        #pragma unroll
        for (int d = 0; d < AD; d++) {
            float v = __ldg(p + (size_t)d * RR);
            s1 += v;
            s2 += v * v;
            t_s[m][j][d] = valid * v;
        }
        // sum_{d1,d2}(t_d1 - t_d2)^2 = 2*D*S2 - 2*S1^2
        sqv[m][j]    = valid * (2.0f * (float)AD * s2 - 2.0f * s1 * s1);
        validf[m][j] = valid;
    }
    __syncthreads();

    // ---- Phase 2: per-person counts + pull_p ----
    if (tid < MP) {
        const int m = tid;
        float cnt = 0.0f, sq = 0.0f;
        #pragma unroll
        for (int j = 0; j < NJ; j++) {
            cnt += validf[m][j];
            sq  += sqv[m][j];
        }
        float sc = fmaxf(cnt, 1.0f);
        safe_cnt[m] = sc;
        float person_valid = (cnt > 0.0f) ? 1.0f : 0.0f;
        pv[m]    = person_valid;
        pullp[m] = person_valid * sq / ((float)(AD * AD) * sc);
    }
    __syncthreads();

    // ---- Phase 3: per-person mean tag (510 threads: one per (m,d)) ----
    if (tid < MP * AD) {
        const int m = tid / AD;
        const int d = tid % AD;
        float s = 0.0f;
        #pragma unroll
        for (int j = 0; j < NJ; j++) s += t_s[m][j][d];
        mean_s[m][d] = s / safe_cnt[m];
    }

    // ---- Phase 4 (thread 0): n_tags + pull scalar ----
    if (tid == 0) {
        float nt = 0.0f, pl = 0.0f;
        #pragma unroll
        for (int m = 0; m < MP; m++) { nt += pv[m]; pl += pullp[m]; }
        ntags_s = nt;
        pull_s  = pl / fmaxf(nt, 1.0f);
    }
    __syncthreads();

    // ---- Phase 5: push — 900 person pairs across 512 threads ----
    float acc = 0.0f;
    for (int pair = tid; pair < MP * MP; pair += blockDim.x) {
        const int m1 = pair / MP;
        const int m2 = pair % MP;
        float w = pv[m1] * pv[m2];
        if (w != 0.0f) {
            float s = 0.0f;
            #pragma unroll
            for (int d = 0; d < AD; d++) {
                float df = mean_s[m1][d] - mean_s[m2][d];
                s += expf(-df * df);
            }
            acc += s * (1.0f / (float)AD);
        }
    }
    // warp reduce + shared atomic
    #pragma unroll
    for (int o = 16; o > 0; o >>= 1)
        acc += __shfl_down_sync(0xffffffffu, acc, o);
    if ((tid & 31) == 0) atomicAdd(&push_acc, acc);
    __syncthreads();

    if (tid == 0) {
        float nt = ntags_s;
        float denom = fmaxf(nt, 1.0f);
        float push = (nt >= 2.0f) ? (push_acc / (denom * denom)) : 0.0f;
        out[b]         = push;   // push[16] first
        out[BATCH + b] = pull_s; // then pull[16]
    }
}

extern "C" void kernel_launch(void* const* d_in, const int* in_sizes, int n_in,
                              void* d_out, int out_size)
{
    const float* tags   = (const float*)d_in[0];
    const int*   joints = (const int*)d_in[1];
    float*       out    = (float*)d_out;
    ae_loss_kernel<<<BATCH, 512>>>(tags, joints, out);
}

// round 5
// speedup vs baseline: 1.1831x; 1.1831x over previous
#include <cuda_runtime.h>
#include <cuda_bf16.h>

#define BATCH 16
#define MP 30      // max people
#define NJ 17      // joints
#define AD 17      // ae tag dim
#define RES 512
#define RR (RES*RES)

#define TOTAL_ELEMS (BATCH * MP * NJ * AD)   // 147456

// scratch: masked gathered tags t[b][m][j][d] (0 when joint invisible)
__device__ float g_scratch[TOTAL_ELEMS];

// ---------------------------------------------------------------------------
// Kernel 1: scattered gather, one thread per (b,m,j,d), spread over all SMs.
// Invisible joints contribute exactly 0 everywhere downstream -> skip the load.
// ---------------------------------------------------------------------------
__global__ __launch_bounds__(256)
void ae_gather_kernel(const float* __restrict__ tags,
                      const int*   __restrict__ joints)
{
    int e = blockIdx.x * blockDim.x + threadIdx.x;
    if (e >= TOTAL_ELEMS) return;

    const int d  = e % AD;
    const int jj = e / AD;               // global joint id in [0, B*MP*NJ)
    const int b  = jj / (MP * NJ);

    const int idx = __ldg(&joints[jj * 2 + 0]);
    const int vis = __ldg(&joints[jj * 2 + 1]);

    float v = 0.0f;
    if (vis > 0) {
        int off = idx % RR;
        if (off < 0) off += RR;
        const int x = off % RES;         // first spatial axis (torch convention)
        const int y = off / RES;
        v = __ldg(tags + (size_t)b * AD * RR + (size_t)d * RR
                       + (size_t)x * RES + y);
    }
    g_scratch[e] = v;
}

// ---------------------------------------------------------------------------
// Kernel 2: per-image reduction from compact scratch (coalesced reads).
// ---------------------------------------------------------------------------
__global__ __launch_bounds__(512, 1)
void ae_reduce_kernel(const int* __restrict__ joints,
                      float*     __restrict__ out)
{
    const int b   = blockIdx.x;
    const int tid = threadIdx.x;

    __shared__ float t_s[MP][NJ][AD];   // masked tag vectors
    __shared__ float sqv[MP][NJ];       // valid * sum_{d1,d2}(t_d1-t_d2)^2
    __shared__ float validf[MP][NJ];
    __shared__ float safe_cnt[MP];
    __shared__ float pullp[MP];
    __shared__ float pv[MP];
    __shared__ float mean_s[MP][AD];
    __shared__ float ntags_s;
    __shared__ float pull_s;
    __shared__ float push_acc;

    const int* jt_b = joints + b * MP * NJ * 2;
    const float* sc_b = g_scratch + (size_t)b * MP * NJ * AD;

    if (tid == 0) push_acc = 0.0f;

    // ---- per-joint: read 17 masked floats, compute s1/s2 ----
    if (tid < MP * NJ) {
        const int m = tid / NJ;
        const int j = tid % NJ;
        const int vis = jt_b[tid * 2 + 1];
        const float valid = (vis > 0) ? 1.0f : 0.0f;

        const float* p = sc_b + (size_t)tid * AD;
        float s1 = 0.0f, s2 = 0.0f;
        #pragma unroll
        for (int d = 0; d < AD; d++) {
            float v = __ldg(p + d);      // already masked by gather kernel
            s1 += v;
            s2 += v * v;
            t_s[m][j][d] = v;
        }
        // valid * sum_{d1,d2}(t_d1 - t_d2)^2 = valid * (2*D*S2 - 2*S1^2)
        sqv[m][j]    = valid * (2.0f * (float)AD * s2 - 2.0f * s1 * s1);
        validf[m][j] = valid;
    }
    __syncthreads();

    // ---- per-person counts + pull_p ----
    if (tid < MP) {
        const int m = tid;
        float cnt = 0.0f, sq = 0.0f;
        #pragma unroll
        for (int j = 0; j < NJ; j++) {
            cnt += validf[m][j];
            sq  += sqv[m][j];
        }
        float scn = fmaxf(cnt, 1.0f);
        safe_cnt[m] = scn;
        float person_valid = (cnt > 0.0f) ? 1.0f : 0.0f;
        pv[m]    = person_valid;
        pullp[m] = person_valid * sq / ((float)(AD * AD) * scn);
    }
    __syncthreads();

    // ---- per-person mean tag: one thread per (m,d) ----
    if (tid < MP * AD) {
        const int m = tid / AD;
        const int d = tid % AD;
        float s = 0.0f;
        #pragma unroll
        for (int j = 0; j < NJ; j++) s += t_s[m][j][d];
        mean_s[m][d] = s / safe_cnt[m];
    }

    // ---- n_tags + pull scalar ----
    if (tid == 0) {
        float nt = 0.0f, pl = 0.0f;
        #pragma unroll
        for (int m = 0; m < MP; m++) { nt += pv[m]; pl += pullp[m]; }
        ntags_s = nt;
        pull_s  = pl / fmaxf(nt, 1.0f);
    }
    __syncthreads();

    // ---- push: 900 person pairs across 512 threads ----
    float acc = 0.0f;
    for (int pair = tid; pair < MP * MP; pair += blockDim.x) {
        const int m1 = pair / MP;
        const int m2 = pair % MP;
        float w = pv[m1] * pv[m2];
        if (w != 0.0f) {
            float s = 0.0f;
            #pragma unroll
            for (int d = 0; d < AD; d++) {
                float df = mean_s[m1][d] - mean_s[m2][d];
                s += expf(-df * df);
            }
            acc += s * (1.0f / (float)AD);
        }
    }
    #pragma unroll
    for (int o = 16; o > 0; o >>= 1)
        acc += __shfl_down_sync(0xffffffffu, acc, o);
    if ((tid & 31) == 0) atomicAdd(&push_acc, acc);
    __syncthreads();

    if (tid == 0) {
        float nt = ntags_s;
        float denom = fmaxf(nt, 1.0f);
        float push = (nt >= 2.0f) ? (push_acc / (denom * denom)) : 0.0f;
        out[b]         = push;   // push[16]
        out[BATCH + b] = pull_s; // pull[16]
    }
}

extern "C" void kernel_launch(void* const* d_in, const int* in_sizes, int n_in,
                              void* d_out, int out_size)
{
    const float* tags   = (const float*)d_in[0];
    const int*   joints = (const int*)d_in[1];
    float*       out    = (float*)d_out;

    const int threads = 256;
    const int blocks  = (TOTAL_ELEMS + threads - 1) / threads;  // 576
    ae_gather_kernel<<<blocks, threads>>>(tags, joints);
    ae_reduce_kernel<<<BATCH, 512>>>(joints, out);
}

// round 6
// speedup vs baseline: 1.1866x; 1.0029x over previous
#include <cuda_runtime.h>
#include <cuda_bf16.h>

#define BATCH 16
#define MP 30      // max people
#define NJ 17      // joints
#define AD 17      // ae tag dim
#define RES 512
#define RR (RES*RES)

#define TOTAL_ELEMS (BATCH * MP * NJ * AD)   // 147456
#define GRID_CTAS 148
#define BLOCK_THREADS 512

// scratch: masked gathered tags t[b][m][j][d] (0 when joint invisible)
__device__ float g_scratch[TOTAL_ELEMS];
// self-resetting grid barrier state (zero-initialized; gen monotonic across replays)
__device__ unsigned g_bar_count = 0;
__device__ volatile unsigned g_bar_gen = 0;

__global__ __launch_bounds__(BLOCK_THREADS, 1)
void ae_fused_kernel(const float* __restrict__ tags,
                     const int*   __restrict__ joints,
                     float*       __restrict__ out)
{
    const int tid = threadIdx.x;

    // ================= Phase A: gather across ALL SMs =================
    {
        const int gsize = GRID_CTAS * BLOCK_THREADS;   // 75776
        for (int e = blockIdx.x * BLOCK_THREADS + tid; e < TOTAL_ELEMS; e += gsize) {
            const int d  = e % AD;
            const int jj = e / AD;               // global joint id [0, B*MP*NJ)
            const int b  = jj / (MP * NJ);

            const int idx = __ldg(&joints[jj * 2 + 0]);
            const int vis = __ldg(&joints[jj * 2 + 1]);

            float v = 0.0f;
            if (vis > 0) {
                int off = idx % RR;
                if (off < 0) off += RR;
                const int x = off % RES;         // first spatial axis (torch convention)
                const int y = off / RES;
                v = __ldg(tags + (size_t)b * AD * RR + (size_t)d * RR
                               + (size_t)x * RES + y);
            }
            g_scratch[e] = v;
        }
    }
    __syncthreads();

    // ================= grid barrier (sense-reversing, self-resetting) ====
    if (tid == 0) {
        __threadfence();                          // publish this CTA's scratch writes
        unsigned gen = g_bar_gen;                 // read phase BEFORE arriving
        unsigned t = atomicAdd(&g_bar_count, 1u);
        if (t == GRID_CTAS - 1) {
            g_bar_count = 0;                      // reset for next replay
            __threadfence();
            g_bar_gen = gen + 1;                  // release
        } else {
            while (g_bar_gen == gen) { }          // spin on L2 line
        }
        __threadfence();                          // acquire
    }
    __syncthreads();

    if (blockIdx.x >= BATCH) return;

    // ================= Phase B: per-image reduction (CTAs 0..15) =========
    const int b = blockIdx.x;

    __shared__ float t_s[MP][NJ][AD];   // masked tag vectors
    __shared__ float sqv[MP][NJ];       // valid * sum_{d1,d2}(t_d1-t_d2)^2
    __shared__ float validf[MP][NJ];
    __shared__ float safe_cnt[MP];
    __shared__ float pullp[MP];
    __shared__ float pv[MP];
    __shared__ float mean_s[MP][AD];
    __shared__ float ntags_s;
    __shared__ float pull_s;
    __shared__ float push_acc;

    const int*   jt_b = joints + b * MP * NJ * 2;
    const float* sc_b = g_scratch + (size_t)b * MP * NJ * AD;

    if (tid == 0) push_acc = 0.0f;

    // ---- per-joint: read 17 masked floats, compute s1/s2 ----
    if (tid < MP * NJ) {
        const int m = tid / NJ;
        const int j = tid % NJ;
        const int vis = jt_b[tid * 2 + 1];
        const float valid = (vis > 0) ? 1.0f : 0.0f;

        const float* p = sc_b + (size_t)tid * AD;
        float s1 = 0.0f, s2 = 0.0f;
        #pragma unroll
        for (int d = 0; d < AD; d++) {
            float v = p[d];              // already masked by gather phase
            s1 += v;
            s2 += v * v;
            t_s[m][j][d] = v;
        }
        // valid * sum_{d1,d2}(t_d1 - t_d2)^2 = valid * (2*D*S2 - 2*S1^2)
        sqv[m][j]    = valid * (2.0f * (float)AD * s2 - 2.0f * s1 * s1);
        validf[m][j] = valid;
    }
    __syncthreads();

    // ---- per-person counts + pull_p ----
    if (tid < MP) {
        const int m = tid;
        float cnt = 0.0f, sq = 0.0f;
        #pragma unroll
        for (int j = 0; j < NJ; j++) {
            cnt += validf[m][j];
            sq  += sqv[m][j];
        }
        float scn = fmaxf(cnt, 1.0f);
        safe_cnt[m] = scn;
        float person_valid = (cnt > 0.0f) ? 1.0f : 0.0f;
        pv[m]    = person_valid;
        pullp[m] = person_valid * sq / ((float)(AD * AD) * scn);
    }
    __syncthreads();

    // ---- per-person mean tag: one thread per (m,d) ----
    if (tid < MP * AD) {
        const int m = tid / AD;
        const int d = tid % AD;
        float s = 0.0f;
        #pragma unroll
        for (int j = 0; j < NJ; j++) s += t_s[m][j][d];
        mean_s[m][d] = s / safe_cnt[m];
    }

    // ---- n_tags + pull scalar ----
    if (tid == 0) {
        float nt = 0.0f, pl = 0.0f;
        #pragma unroll
        for (int m = 0; m < MP; m++) { nt += pv[m]; pl += pullp[m]; }
        ntags_s = nt;
        pull_s  = pl / fmaxf(nt, 1.0f);
    }
    __syncthreads();

    // ---- push: 900 person pairs across 512 threads (fast exp) ----
    float acc = 0.0f;
    for (int pair = tid; pair < MP * MP; pair += BLOCK_THREADS) {
        const int m1 = pair / MP;
        const int m2 = pair % MP;
        float w = pv[m1] * pv[m2];
        if (w != 0.0f) {
            float s = 0.0f;
            #pragma unroll
            for (int d = 0; d < AD; d++) {
                float df = mean_s[m1][d] - mean_s[m2][d];
                s += __expf(-df * df);    // MUFU.EX2 path, rel err ~2^-21
            }
            acc += s * (1.0f / (float)AD);
        }
    }
    #pragma unroll
    for (int o = 16; o > 0; o >>= 1)
        acc += __shfl_down_sync(0xffffffffu, acc, o);
    if ((tid & 31) == 0) atomicAdd(&push_acc, acc);
    __syncthreads();

    if (tid == 0) {
        float nt = ntags_s;
        float denom = fmaxf(nt, 1.0f);
        float push = (nt >= 2.0f) ? (push_acc / (denom * denom)) : 0.0f;
        out[b]         = push;   // push[16]
        out[BATCH + b] = pull_s; // pull[16]
    }
}

extern "C" void kernel_launch(void* const* d_in, const int* in_sizes, int n_in,
                              void* d_out, int out_size)
{
    const float* tags   = (const float*)d_in[0];
    const int*   joints = (const int*)d_in[1];
    float*       out    = (float*)d_out;

    ae_fused_kernel<<<GRID_CTAS, BLOCK_THREADS>>>(tags, joints, out);
}